// round 13
// baseline (speedup 1.0000x reference)
#include <cuda_runtime.h>
#include <cuda_fp16.h>
#include <cstdint>

// ---------------------------------------------------------------------------
// y[b,l,h,w] = sum_{j,k,i} A[(b,h,w),(j,k,i)] * W[j,k,i,l]
// GEMM: D[512, 6272] = Wmat[512,2304] * Amat[6272,2304]^T  (fp16 in, f32 acc)
// v13: prep at 512 threads/CTA (2x warps in flight); split-K reduce fused
// into the GEMM epilogue via per-tile semaphore (last CTA of 3 sums the
// partials in fixed order and scatters to NCHW).  No separate reduce kernel.
// ---------------------------------------------------------------------------

#define NKC    72          // 2304 / 32 K blocks
#define MT     4           // M tiles of 128  (M = 512)
#define NTT    49          // N tiles of 128  (N = 6272)
#define NTILES 196         // MT * NTT
#define BLKB   8192        // one 128x32 fp16 tile block (128 rows x 64 B)
#define STAGE_BYTES 32768  // 64-K stage: 2 W blocks + 2 A blocks
#define STAGES 3
#define KSPLIT 3
#define NSTS   12          // 64-K stages per split (36 / 3)
#define GEMM_SMEM (1024 + STAGES * STAGE_BYTES)   // 99328 (x2 = 194K < 227K)

#define PREP_SMEM (25088 * 4)          // x[b] verbatim (100352 B)

__device__ __align__(128) unsigned char g_W[MT * NKC * BLKB];        // 2.36 MB
__device__ __align__(128) unsigned char g_A[NTT * NKC * BLKB];       // 28.9 MB
__device__ __align__(128) float g_P[KSPLIT * NTILES * 16384];        // 38.5 MB
__device__ int g_cnt[NTILES];

// ---------------------------------------------------------------------------
// helpers
// ---------------------------------------------------------------------------
__device__ __forceinline__ uint32_t smem_u32(const void* p) {
    uint32_t a;
    asm("{ .reg .u64 t; cvta.to.shared.u64 t, %1; cvt.u32.u64 %0, t; }"
        : "=r"(a) : "l"(p));
    return a;
}
__device__ __forceinline__ void mbar_init(uint32_t a, uint32_t cnt) {
    asm volatile("mbarrier.init.shared.b64 [%0], %1;" :: "r"(a), "r"(cnt) : "memory");
}
__device__ __forceinline__ void mbar_expect_tx(uint32_t a, uint32_t bytes) {
    asm volatile("mbarrier.arrive.expect_tx.shared.b64 _, [%0], %1;"
                 :: "r"(a), "r"(bytes) : "memory");
}
__device__ __forceinline__ void mbar_wait(uint32_t mbar, uint32_t parity) {
    uint32_t done;
    asm volatile("{\n\t.reg .pred p;\n\t"
                 "mbarrier.try_wait.parity.acquire.cta.shared::cta.b64 p, [%1], %2;\n\t"
                 "selp.b32 %0,1,0,p;\n\t}"
                 : "=r"(done) : "r"(mbar), "r"(parity) : "memory");
    while (!done) {
        asm volatile("{\n\t.reg .pred p;\n\t"
                     "mbarrier.try_wait.parity.acquire.cta.shared::cta.b64 p, [%1], %2, 0x989680;\n\t"
                     "selp.b32 %0,1,0,p;\n\t}"
                     : "=r"(done) : "r"(mbar), "r"(parity) : "memory");
    }
}
__device__ __forceinline__ void bulk_g2s(uint32_t dst, const void* src,
                                         uint32_t bytes, uint32_t mbar) {
    asm volatile("cp.async.bulk.shared::cluster.global.mbarrier::complete_tx::bytes "
                 "[%0], [%1], %2, [%3];"
                 :: "r"(dst), "l"(src), "r"(bytes), "r"(mbar) : "memory");
}
__device__ __forceinline__ void ldsm4(uint32_t* r, uint32_t addr) {
    asm volatile("ldmatrix.sync.aligned.m8n8.x4.shared.b16 {%0,%1,%2,%3}, [%4];"
                 : "=r"(r[0]), "=r"(r[1]), "=r"(r[2]), "=r"(r[3]) : "r"(addr));
}
__device__ __forceinline__ void mma16816(float* c, const uint32_t* a, const uint32_t* b) {
    asm volatile("mma.sync.aligned.m16n8k16.row.col.f32.f16.f16.f32 "
                 "{%0,%1,%2,%3}, {%4,%5,%6,%7}, {%8,%9}, {%0,%1,%2,%3};"
                 : "+f"(c[0]), "+f"(c[1]), "+f"(c[2]), "+f"(c[3])
                 : "r"(a[0]), "r"(a[1]), "r"(a[2]), "r"(a[3]),
                   "r"(b[0]), "r"(b[1]));
}
__device__ __forceinline__ uint32_t pack_f16x2(float lo, float hi) {
    uint32_t u;
    asm("cvt.rn.f16x2.f32 %0, %1, %2;" : "=r"(u) : "f"(hi), "f"(lo));
    return u;
}

// ---------------------------------------------------------------------------
// prep (512 threads): blocks [0,128) build g_A for batch b;
//                     blocks [128,272) build g_W (chunk-swizzled).
// Block 0 also zeroes the split-K semaphores (graph-replay safe).
// ---------------------------------------------------------------------------
__global__ __launch_bounds__(512, 1) void prep_kernel(const float* __restrict__ x,
                                                      const float* __restrict__ Wt) {
    extern __shared__ float dynsm[];
    int tid = threadIdx.x;

    if (blockIdx.x >= 128) {
        // ---- wtrans: W[j,k,i,l] -> g_W fp16 [mt][ks][128 x 32] swizzled ----
        int t = blockIdx.x - 128;                   // 0..143
        int mt = t / 36;
        int K0 = (t - mt * 36) * 64;
        int L0 = mt * 128;
        int ks0 = K0 >> 5;
        float* ws = dynsm;                          // [64][129]

        int lx = tid & 127;
#pragma unroll
        for (int kl = (tid >> 7); kl < 64; kl += 4) {
            int kk = K0 + kl;
            int j = kk & 255, ki = kk >> 8;
            int k = (ki * 11) >> 5, i = ki - 3 * k;
            ws[kl * 129 + lx] = Wt[(size_t)((j * 3 + k) * 3 + i) * 512 + L0 + lx];
        }
        __syncthreads();

        int u = tid & 15;                           // u>>2 = chunk, u&3 = word
        int rbase = tid >> 4;                       // 0..31
#pragma unroll
        for (int rr = 0; rr < 4; rr++) {
            int rloc = rr * 32 + rbase;             // 0..127
            uint32_t swc = ((uint32_t)(u >> 2) ^ ((rloc >> 1) & 3)) << 4;
#pragma unroll
            for (int ksb = 0; ksb < 2; ksb++) {
                float v0 = ws[(ksb * 32 + 2 * u) * 129 + rloc];
                float v1 = ws[(ksb * 32 + 2 * u + 1) * 129 + rloc];
                *reinterpret_cast<uint32_t*>(
                    g_W + (size_t)(mt * NKC + ks0 + ksb) * BLKB
                    + rloc * 64 + swc + (u & 3) * 4) = pack_f16x2(v0, v1);
            }
        }
        return;
    }

    // ---- A build for batch b ----
    if (blockIdx.x == 0 && tid < NTILES) g_cnt[tid] = 0;   // split-K semaphores

    float* xs = dynsm;                              // x[b] verbatim: xs[c*49+hw]
    int b = blockIdx.x;
    const float4* xb4 = reinterpret_cast<const float4*>(x + (size_t)b * 25088);
    float4* xs4 = reinterpret_cast<float4*>(xs);

    // Phase 1: verbatim copy (coalesced, conflict-free, full MLP)
    for (int v = tid; v < 6272; v += 512) xs4[v] = xb4[v];
    __syncthreads();

    int wid = tid >> 5, lane = tid & 31;

    // Phase 2: 77 (s,w2) combos, s in 1..11.  Warp computes the 512B D-row
    // in registers (lane: j = 8*lane .. 8*lane+7, strided LDS) and scatters.
    for (int combo = wid; combo < 77; combo += 16) {
        int s = combo / 7 + 1, w2 = combo - (s - 1) * 7;
        int rpA, rpB;
        if (s < 9) { rpA = s - 1; rpB = s - 2; }
        else       { rpA = s - 10; rpB = s - 4; }
        bool g1 = (unsigned)rpA < 7u, g2 = (unsigned)rpB < 7u;

        float va[8], vb[8];
#pragma unroll
        for (int jj = 0; jj < 8; jj++) { va[jj] = 0.f; vb[jj] = 0.f; }
        if (g1) {
            const float* p = xs + (lane * 8) * 49 + rpA * 7 + w2;
#pragma unroll
            for (int jj = 0; jj < 8; jj++) va[jj] = p[jj * 49];
        }
        if (g2) {
            const float* p = xs + (256 + lane * 8) * 49 + rpB * 7 + w2;
#pragma unroll
            for (int jj = 0; jj < 8; jj++) vb[jj] = p[jj * 49];
        }
        uint4 o;
        o.x = pack_f16x2(va[0] + vb[0], va[1] + vb[1]);
        o.y = pack_f16x2(va[2] + vb[2], va[3] + vb[3]);
        o.z = pack_f16x2(va[4] + vb[4], va[5] + vb[5]);
        o.w = pack_f16x2(va[6] + vb[6], va[7] + vb[7]);

        int ww1 = (w2 + 1) % 7;
        int jc = lane >> 2, cw = lane & 3;
        int hlo, hhi;
        if (s >= 9) { hlo = 0; hhi = 0; }
        else { hlo = (s - 2 > 1) ? s - 2 : 1; hhi = (s < 6) ? s : 6; }
#pragma unroll 1
        for (int h = hlo; h <= hhi; h++) {
            int k = (s >= 9) ? (s - 9) : (s - h);
#pragma unroll
            for (int i = 0; i < 3; i++) {
                int w = ww1 + 1 - i;
                if ((unsigned)w < 7u) {
                    int ki = k * 3 + i;
                    int n = b * 49 + h * 7 + w;
                    int nt = n >> 7, row = n & 127;
                    int chunk = cw ^ ((row >> 1) & 3);
                    *reinterpret_cast<uint4*>(
                        g_A + ((size_t)(nt * NKC + ki * 8 + jc) << 13)
                        + row * 64 + chunk * 16) = o;
                }
            }
        }
    }

    // Phase 3: zero the gated rows: (w=0,i=0) and (w=6,i=2), all h,k,jc.
    const uint4 z4 = {0, 0, 0, 0};
    for (int t = tid; t < 1344; t += 512) {
        int c = t & 3;
        int rown = t >> 2;                  // 0..335
        int jc = rown & 7;
        int zz = rown >> 3;                 // 0..41
        int zi = zz / 21;                   // 0:(w=0,i=0)  1:(w=6,i=2)
        int rem = zz - zi * 21;
        int k = rem / 7, h = rem - k * 7;
        int ki = k * 3 + (zi ? 2 : 0);
        int w = zi ? 6 : 0;
        int n = b * 49 + h * 7 + w;
        int nt = n >> 7, row = n & 127;
        *reinterpret_cast<uint4*>(
            g_A + ((size_t)(nt * NKC + ki * 8 + jc) << 13)
            + row * 64 + c * 16) = z4;
    }
}

// ---------------------------------------------------------------------------
// GEMM.  588 CTAs = 3 splits x (4 mt x 49 nt), tile 128x128 x K768.
// 12 stages of K=64 (32KB), 3-deep, 2 bulk copies per stage, occ 2.
// Fused split-K reduce: last CTA per tile sums 3 partials (fixed sp order,
// bit-deterministic) and scatters to out[b][l][h][w].
// ---------------------------------------------------------------------------
__global__ __launch_bounds__(256, 2) void gemm_kernel(float* __restrict__ out) {
    extern __shared__ __align__(1024) unsigned char smem[];
    __shared__ int s_last;
    uint32_t sb = smem_u32(smem);
    const uint32_t FULLB = sb;                 // 3 x 8B mbarriers
    const uint32_t DATA = sb + 1024;

    int tid = threadIdx.x, wid = tid >> 5, lane = tid & 31;
    int sp = blockIdx.x / NTILES;
    int tile = blockIdx.x - sp * NTILES;
    int mt = tile / NTT, nt = tile - mt * NTT;
    int wm = wid & 1, wn = wid >> 1;           // 2(M) x 4(N)

    const unsigned char* wsrc = g_W + (size_t)mt * NKC * BLKB
                                + (size_t)sp * NSTS * 16384;
    const unsigned char* asrc = g_A + (size_t)nt * NKC * BLKB
                                + (size_t)sp * NSTS * 16384;

    if (tid == 0) {
#pragma unroll
        for (int s = 0; s < STAGES; s++) mbar_init(FULLB + 8 * s, 1);
    }
    asm volatile("fence.proxy.async.shared::cta;" ::: "memory");
    __syncthreads();

    if (tid == 0) {
#pragma unroll
        for (int ip = 0; ip < STAGES - 1; ip++) {
            uint32_t mb = FULLB + 8 * ip;
            mbar_expect_tx(mb, STAGE_BYTES);
            bulk_g2s(DATA + ip * STAGE_BYTES, wsrc + (size_t)ip * 16384, 16384, mb);
            bulk_g2s(DATA + ip * STAGE_BYTES + 16384, asrc + (size_t)ip * 16384, 16384, mb);
        }
    }

    // ldsm per-thread addressing (chunk swizzle: ^ ((row>>1)&3))
    uint32_t arow = wm * 64 + (lane & 15);
    uint32_t axor = (arow >> 1) & 3;
    uint32_t ahi = lane >> 4;
    uint32_t aoffb = arow * 64;
    uint32_t brow = wn * 32 + (lane & 7) + ((lane & 16) >> 1);
    uint32_t bxor = (brow >> 1) & 3;
    uint32_t bhi = (lane >> 3) & 1;
    uint32_t boffb = brow * 64;

    float acc[4][4][4];
#pragma unroll
    for (int mi = 0; mi < 4; mi++)
#pragma unroll
        for (int ni = 0; ni < 4; ni++)
#pragma unroll
            for (int r = 0; r < 4; r++) acc[mi][ni][r] = 0.f;

#pragma unroll 1
    for (int st = 0; st < NSTS; st++) {
        int buf = st % 3;
        mbar_wait(FULLB + 8 * buf, (uint32_t)((st / 3) & 1));
        uint32_t sbuf = DATA + buf * STAGE_BYTES;
#pragma unroll
        for (int kst = 0; kst < 4; kst++) {
            uint32_t wbo = (uint32_t)(kst >> 1) * 8192;
            uint32_t ac = (((kst & 1) * 2 + ahi) ^ axor) << 4;
            uint32_t bc = (((kst & 1) * 2 + bhi) ^ bxor) << 4;
            uint32_t a[4][4], bfr[2][4];
#pragma unroll
            for (int mi = 0; mi < 4; mi++)
                ldsm4(a[mi], sbuf + wbo + aoffb + mi * 1024 + ac);
#pragma unroll
            for (int np = 0; np < 2; np++)
                ldsm4(bfr[np], sbuf + 16384 + wbo + boffb + np * 1024 + bc);
#pragma unroll
            for (int mi = 0; mi < 4; mi++)
#pragma unroll
                for (int ni = 0; ni < 4; ni++)
                    mma16816(acc[mi][ni], a[mi], &bfr[ni >> 1][(ni & 1) * 2]);
        }
        __syncthreads();
        if (tid == 0) {
            int ip = st + STAGES - 1;
            if (ip < NSTS) {
                int pb = ip % 3;
                uint32_t mb = FULLB + 8 * pb;
                mbar_expect_tx(mb, STAGE_BYTES);
                bulk_g2s(DATA + pb * STAGE_BYTES, wsrc + (size_t)ip * 16384, 16384, mb);
                bulk_g2s(DATA + pb * STAGE_BYTES + 16384, asrc + (size_t)ip * 16384, 16384, mb);
            }
        }
    }

    // epilogue: store dense f32 partial (float2)
    float2* pdst = reinterpret_cast<float2*>(g_P + (size_t)blockIdx.x * 16384);
#pragma unroll
    for (int mi = 0; mi < 4; mi++) {
        int r0 = wm * 64 + mi * 16 + (lane >> 2);
#pragma unroll
        for (int ni = 0; ni < 4; ni++) {
            int c0 = wn * 32 + ni * 8 + 2 * (lane & 3);
#pragma unroll
            for (int rp = 0; rp < 2; rp++) {
                int row = r0 + rp * 8;
                float2 v = { acc[mi][ni][rp * 2], acc[mi][ni][rp * 2 + 1] };
                pdst[(row * 128 + c0) >> 1] = v;
            }
        }
    }

    // split-K semaphore: last CTA of the 3 reduces (fixed sp order)
    __threadfence();
    __syncthreads();
    if (tid == 0) s_last = (atomicAdd(&g_cnt[tile], 1) == KSPLIT - 1);
    __syncthreads();
    if (!s_last) return;
    __threadfence();

    const float4* p0 = reinterpret_cast<const float4*>(g_P + (size_t)tile * 16384);
    const float4* p1 = p0 + (size_t)NTILES * 4096;
    const float4* p2 = p1 + (size_t)NTILES * 4096;
#pragma unroll 4
    for (int it = 0; it < 16; it++) {
        int v = it * 256 + tid;                // float4 index, 4096 per tile
        float4 a = p0[v], b4 = p1[v], c = p2[v];
        float s0 = a.x + b4.x + c.x;
        float s1 = a.y + b4.y + c.y;
        float s2 = a.z + b4.z + c.z;
        float s3 = a.w + b4.w + c.w;
        int idx = v * 4;
        int row = idx >> 7, col = idx & 127;
        int m = mt * 128 + row;
        int n = nt * 128 + col;
        int bb = n / 49, hw = n - bb * 49;
        float* o = out + (size_t)m * 49;
        o[(size_t)bb * 25088 + hw] = s0; if (++hw == 49) { hw = 0; bb++; }
        o[(size_t)bb * 25088 + hw] = s1; if (++hw == 49) { hw = 0; bb++; }
        o[(size_t)bb * 25088 + hw] = s2; if (++hw == 49) { hw = 0; bb++; }
        o[(size_t)bb * 25088 + hw] = s3;
    }
}

// ---------------------------------------------------------------------------
extern "C" void kernel_launch(void* const* d_in, const int* in_sizes, int n_in,
                              void* d_out, int out_size) {
    const float* x  = (const float*)d_in[0];   // [128,512,7,7]
    const float* Wt = (const float*)d_in[1];   // [256,3,3,512]
    float* out = (float*)d_out;                // [128,512,7,7]

    cudaFuncSetAttribute(prep_kernel, cudaFuncAttributeMaxDynamicSharedMemorySize,
                         PREP_SMEM);
    cudaFuncSetAttribute(gemm_kernel, cudaFuncAttributeMaxDynamicSharedMemorySize,
                         GEMM_SMEM);

    prep_kernel<<<272, 512, PREP_SMEM>>>(x, Wt);
    gemm_kernel<<<KSPLIT * NTILES, 256, GEMM_SMEM>>>(out);
}

// round 14
// speedup vs baseline: 1.0299x; 1.0299x over previous
#include <cuda_runtime.h>
#include <cuda_fp16.h>
#include <cstdint>

// ---------------------------------------------------------------------------
// y[b,l,h,w] = sum_{j,k,i} A[(b,h,w),(j,k,i)] * W[j,k,i,l]
// GEMM: D[512, 6272] = Wmat[512,2304] * Amat[6272,2304]^T  (fp16 in, f32 acc)
// v14: best-of-both: 512-thread prep (v13) + split-K=3 GEMM with dense f32
// partials + SEPARATE 392-CTA reduce kernel (v12).  No fusion semaphore.
// ---------------------------------------------------------------------------

#define NKC    72          // 2304 / 32 K blocks
#define MT     4           // M tiles of 128  (M = 512)
#define NTT    49          // N tiles of 128  (N = 6272)
#define NTILES 196         // MT * NTT
#define BLKB   8192        // one 128x32 fp16 tile block (128 rows x 64 B)
#define STAGE_BYTES 32768  // 64-K stage: 2 W blocks + 2 A blocks
#define STAGES 3
#define KSPLIT 3
#define NSTS   12          // 64-K stages per split (36 / 3)
#define GEMM_SMEM (1024 + STAGES * STAGE_BYTES)   // 99328 (x2 = 194K < 227K)

#define PREP_SMEM (25088 * 4)          // x[b] verbatim (100352 B)

__device__ __align__(128) unsigned char g_W[MT * NKC * BLKB];        // 2.36 MB
__device__ __align__(128) unsigned char g_A[NTT * NKC * BLKB];       // 28.9 MB
__device__ __align__(128) float g_P[KSPLIT * NTILES * 16384];        // 38.5 MB

// ---------------------------------------------------------------------------
// helpers
// ---------------------------------------------------------------------------
__device__ __forceinline__ uint32_t smem_u32(const void* p) {
    uint32_t a;
    asm("{ .reg .u64 t; cvta.to.shared.u64 t, %1; cvt.u32.u64 %0, t; }"
        : "=r"(a) : "l"(p));
    return a;
}
__device__ __forceinline__ void mbar_init(uint32_t a, uint32_t cnt) {
    asm volatile("mbarrier.init.shared.b64 [%0], %1;" :: "r"(a), "r"(cnt) : "memory");
}
__device__ __forceinline__ void mbar_expect_tx(uint32_t a, uint32_t bytes) {
    asm volatile("mbarrier.arrive.expect_tx.shared.b64 _, [%0], %1;"
                 :: "r"(a), "r"(bytes) : "memory");
}
__device__ __forceinline__ void mbar_wait(uint32_t mbar, uint32_t parity) {
    uint32_t done;
    asm volatile("{\n\t.reg .pred p;\n\t"
                 "mbarrier.try_wait.parity.acquire.cta.shared::cta.b64 p, [%1], %2;\n\t"
                 "selp.b32 %0,1,0,p;\n\t}"
                 : "=r"(done) : "r"(mbar), "r"(parity) : "memory");
    while (!done) {
        asm volatile("{\n\t.reg .pred p;\n\t"
                     "mbarrier.try_wait.parity.acquire.cta.shared::cta.b64 p, [%1], %2, 0x989680;\n\t"
                     "selp.b32 %0,1,0,p;\n\t}"
                     : "=r"(done) : "r"(mbar), "r"(parity) : "memory");
    }
}
__device__ __forceinline__ void bulk_g2s(uint32_t dst, const void* src,
                                         uint32_t bytes, uint32_t mbar) {
    asm volatile("cp.async.bulk.shared::cluster.global.mbarrier::complete_tx::bytes "
                 "[%0], [%1], %2, [%3];"
                 :: "r"(dst), "l"(src), "r"(bytes), "r"(mbar) : "memory");
}
__device__ __forceinline__ void ldsm4(uint32_t* r, uint32_t addr) {
    asm volatile("ldmatrix.sync.aligned.m8n8.x4.shared.b16 {%0,%1,%2,%3}, [%4];"
                 : "=r"(r[0]), "=r"(r[1]), "=r"(r[2]), "=r"(r[3]) : "r"(addr));
}
__device__ __forceinline__ void mma16816(float* c, const uint32_t* a, const uint32_t* b) {
    asm volatile("mma.sync.aligned.m16n8k16.row.col.f32.f16.f16.f32 "
                 "{%0,%1,%2,%3}, {%4,%5,%6,%7}, {%8,%9}, {%0,%1,%2,%3};"
                 : "+f"(c[0]), "+f"(c[1]), "+f"(c[2]), "+f"(c[3])
                 : "r"(a[0]), "r"(a[1]), "r"(a[2]), "r"(a[3]),
                   "r"(b[0]), "r"(b[1]));
}
__device__ __forceinline__ uint32_t pack_f16x2(float lo, float hi) {
    uint32_t u;
    asm("cvt.rn.f16x2.f32 %0, %1, %2;" : "=r"(u) : "f"(hi), "f"(lo));
    return u;
}

// ---------------------------------------------------------------------------
// prep (512 threads): blocks [0,128) build g_A for batch b;
//                     blocks [128,272) build g_W (chunk-swizzled).
// ---------------------------------------------------------------------------
__global__ __launch_bounds__(512, 1) void prep_kernel(const float* __restrict__ x,
                                                      const float* __restrict__ Wt) {
    extern __shared__ float dynsm[];
    int tid = threadIdx.x;

    if (blockIdx.x >= 128) {
        // ---- wtrans: W[j,k,i,l] -> g_W fp16 [mt][ks][128 x 32] swizzled ----
        int t = blockIdx.x - 128;                   // 0..143
        int mt = t / 36;
        int K0 = (t - mt * 36) * 64;
        int L0 = mt * 128;
        int ks0 = K0 >> 5;
        float* ws = dynsm;                          // [64][129]

        int lx = tid & 127;
#pragma unroll
        for (int kl = (tid >> 7); kl < 64; kl += 4) {
            int kk = K0 + kl;
            int j = kk & 255, ki = kk >> 8;
            int k = (ki * 11) >> 5, i = ki - 3 * k;
            ws[kl * 129 + lx] = Wt[(size_t)((j * 3 + k) * 3 + i) * 512 + L0 + lx];
        }
        __syncthreads();

        int u = tid & 15;                           // u>>2 = chunk, u&3 = word
        int rbase = tid >> 4;                       // 0..31
#pragma unroll
        for (int rr = 0; rr < 4; rr++) {
            int rloc = rr * 32 + rbase;             // 0..127
            uint32_t swc = ((uint32_t)(u >> 2) ^ ((rloc >> 1) & 3)) << 4;
#pragma unroll
            for (int ksb = 0; ksb < 2; ksb++) {
                float v0 = ws[(ksb * 32 + 2 * u) * 129 + rloc];
                float v1 = ws[(ksb * 32 + 2 * u + 1) * 129 + rloc];
                *reinterpret_cast<uint32_t*>(
                    g_W + (size_t)(mt * NKC + ks0 + ksb) * BLKB
                    + rloc * 64 + swc + (u & 3) * 4) = pack_f16x2(v0, v1);
            }
        }
        return;
    }

    // ---- A build for batch b ----
    float* xs = dynsm;                              // x[b] verbatim: xs[c*49+hw]
    int b = blockIdx.x;
    const float4* xb4 = reinterpret_cast<const float4*>(x + (size_t)b * 25088);
    float4* xs4 = reinterpret_cast<float4*>(xs);

    // Phase 1: verbatim copy (coalesced, conflict-free, full MLP)
    for (int v = tid; v < 6272; v += 512) xs4[v] = xb4[v];
    __syncthreads();

    int wid = tid >> 5, lane = tid & 31;

    // Phase 2: 77 (s,w2) combos, s in 1..11.  Warp computes the 512B D-row
    // in registers (lane: j = 8*lane .. 8*lane+7, strided LDS) and scatters.
    for (int combo = wid; combo < 77; combo += 16) {
        int s = combo / 7 + 1, w2 = combo - (s - 1) * 7;
        int rpA, rpB;
        if (s < 9) { rpA = s - 1; rpB = s - 2; }
        else       { rpA = s - 10; rpB = s - 4; }
        bool g1 = (unsigned)rpA < 7u, g2 = (unsigned)rpB < 7u;

        float va[8], vb[8];
#pragma unroll
        for (int jj = 0; jj < 8; jj++) { va[jj] = 0.f; vb[jj] = 0.f; }
        if (g1) {
            const float* p = xs + (lane * 8) * 49 + rpA * 7 + w2;
#pragma unroll
            for (int jj = 0; jj < 8; jj++) va[jj] = p[jj * 49];
        }
        if (g2) {
            const float* p = xs + (256 + lane * 8) * 49 + rpB * 7 + w2;
#pragma unroll
            for (int jj = 0; jj < 8; jj++) vb[jj] = p[jj * 49];
        }
        uint4 o;
        o.x = pack_f16x2(va[0] + vb[0], va[1] + vb[1]);
        o.y = pack_f16x2(va[2] + vb[2], va[3] + vb[3]);
        o.z = pack_f16x2(va[4] + vb[4], va[5] + vb[5]);
        o.w = pack_f16x2(va[6] + vb[6], va[7] + vb[7]);

        int ww1 = (w2 + 1) % 7;
        int jc = lane >> 2, cw = lane & 3;
        int hlo, hhi;
        if (s >= 9) { hlo = 0; hhi = 0; }
        else { hlo = (s - 2 > 1) ? s - 2 : 1; hhi = (s < 6) ? s : 6; }
#pragma unroll 1
        for (int h = hlo; h <= hhi; h++) {
            int k = (s >= 9) ? (s - 9) : (s - h);
#pragma unroll
            for (int i = 0; i < 3; i++) {
                int w = ww1 + 1 - i;
                if ((unsigned)w < 7u) {
                    int ki = k * 3 + i;
                    int n = b * 49 + h * 7 + w;
                    int nt = n >> 7, row = n & 127;
                    int chunk = cw ^ ((row >> 1) & 3);
                    *reinterpret_cast<uint4*>(
                        g_A + ((size_t)(nt * NKC + ki * 8 + jc) << 13)
                        + row * 64 + chunk * 16) = o;
                }
            }
        }
    }

    // Phase 3: zero the gated rows: (w=0,i=0) and (w=6,i=2), all h,k,jc.
    const uint4 z4 = {0, 0, 0, 0};
    for (int t = tid; t < 1344; t += 512) {
        int c = t & 3;
        int rown = t >> 2;                  // 0..335
        int jc = rown & 7;
        int zz = rown >> 3;                 // 0..41
        int zi = zz / 21;                   // 0:(w=0,i=0)  1:(w=6,i=2)
        int rem = zz - zi * 21;
        int k = rem / 7, h = rem - k * 7;
        int ki = k * 3 + (zi ? 2 : 0);
        int w = zi ? 6 : 0;
        int n = b * 49 + h * 7 + w;
        int nt = n >> 7, row = n & 127;
        *reinterpret_cast<uint4*>(
            g_A + ((size_t)(nt * NKC + ki * 8 + jc) << 13)
            + row * 64 + c * 16) = z4;
    }
}

// ---------------------------------------------------------------------------
// GEMM.  588 CTAs = 3 splits x (4 mt x 49 nt), tile 128x128 x K768.
// 12 stages of K=64 (32KB), 3-deep, 2 bulk copies per stage, occ 2.
// Dense f32 partial output to g_P (float2 stores).  Warp grid 2(M) x 4(N).
// ---------------------------------------------------------------------------
__global__ __launch_bounds__(256, 2) void gemm_kernel() {
    extern __shared__ __align__(1024) unsigned char smem[];
    uint32_t sb = smem_u32(smem);
    const uint32_t FULLB = sb;                 // 3 x 8B mbarriers
    const uint32_t DATA = sb + 1024;

    int tid = threadIdx.x, wid = tid >> 5, lane = tid & 31;
    int sp = blockIdx.x / NTILES;
    int tile = blockIdx.x - sp * NTILES;
    int mt = tile / NTT, nt = tile - mt * NTT;
    int wm = wid & 1, wn = wid >> 1;           // 2(M) x 4(N)

    const unsigned char* wsrc = g_W + (size_t)mt * NKC * BLKB
                                + (size_t)sp * NSTS * 16384;
    const unsigned char* asrc = g_A + (size_t)nt * NKC * BLKB
                                + (size_t)sp * NSTS * 16384;

    if (tid == 0) {
#pragma unroll
        for (int s = 0; s < STAGES; s++) mbar_init(FULLB + 8 * s, 1);
    }
    asm volatile("fence.proxy.async.shared::cta;" ::: "memory");
    __syncthreads();

    if (tid == 0) {
#pragma unroll
        for (int ip = 0; ip < STAGES - 1; ip++) {
            uint32_t mb = FULLB + 8 * ip;
            mbar_expect_tx(mb, STAGE_BYTES);
            bulk_g2s(DATA + ip * STAGE_BYTES, wsrc + (size_t)ip * 16384, 16384, mb);
            bulk_g2s(DATA + ip * STAGE_BYTES + 16384, asrc + (size_t)ip * 16384, 16384, mb);
        }
    }

    // ldsm per-thread addressing (chunk swizzle: ^ ((row>>1)&3))
    uint32_t arow = wm * 64 + (lane & 15);
    uint32_t axor = (arow >> 1) & 3;
    uint32_t ahi = lane >> 4;
    uint32_t aoffb = arow * 64;
    uint32_t brow = wn * 32 + (lane & 7) + ((lane & 16) >> 1);
    uint32_t bxor = (brow >> 1) & 3;
    uint32_t bhi = (lane >> 3) & 1;
    uint32_t boffb = brow * 64;

    float acc[4][4][4];
#pragma unroll
    for (int mi = 0; mi < 4; mi++)
#pragma unroll
        for (int ni = 0; ni < 4; ni++)
#pragma unroll
            for (int r = 0; r < 4; r++) acc[mi][ni][r] = 0.f;

#pragma unroll 1
    for (int st = 0; st < NSTS; st++) {
        int buf = st % 3;
        mbar_wait(FULLB + 8 * buf, (uint32_t)((st / 3) & 1));
        uint32_t sbuf = DATA + buf * STAGE_BYTES;
#pragma unroll
        for (int kst = 0; kst < 4; kst++) {
            uint32_t wbo = (uint32_t)(kst >> 1) * 8192;
            uint32_t ac = (((kst & 1) * 2 + ahi) ^ axor) << 4;
            uint32_t bc = (((kst & 1) * 2 + bhi) ^ bxor) << 4;
            uint32_t a[4][4], bfr[2][4];
#pragma unroll
            for (int mi = 0; mi < 4; mi++)
                ldsm4(a[mi], sbuf + wbo + aoffb + mi * 1024 + ac);
#pragma unroll
            for (int np = 0; np < 2; np++)
                ldsm4(bfr[np], sbuf + 16384 + wbo + boffb + np * 1024 + bc);
#pragma unroll
            for (int mi = 0; mi < 4; mi++)
#pragma unroll
                for (int ni = 0; ni < 4; ni++)
                    mma16816(acc[mi][ni], a[mi], &bfr[ni >> 1][(ni & 1) * 2]);
        }
        __syncthreads();
        if (tid == 0) {
            int ip = st + STAGES - 1;
            if (ip < NSTS) {
                int pb = ip % 3;
                uint32_t mb = FULLB + 8 * pb;
                mbar_expect_tx(mb, STAGE_BYTES);
                bulk_g2s(DATA + pb * STAGE_BYTES, wsrc + (size_t)ip * 16384, 16384, mb);
                bulk_g2s(DATA + pb * STAGE_BYTES + 16384, asrc + (size_t)ip * 16384, 16384, mb);
            }
        }
    }

    // epilogue: dense f32 partial tile, float2 stores
    float2* pdst = reinterpret_cast<float2*>(g_P + (size_t)blockIdx.x * 16384);
#pragma unroll
    for (int mi = 0; mi < 4; mi++) {
        int r0 = wm * 64 + mi * 16 + (lane >> 2);
#pragma unroll
        for (int ni = 0; ni < 4; ni++) {
            int c0 = wn * 32 + ni * 8 + 2 * (lane & 3);
#pragma unroll
            for (int rp = 0; rp < 2; rp++) {
                int row = r0 + rp * 8;
                float2 v = { acc[mi][ni][rp * 2], acc[mi][ni][rp * 2 + 1] };
                pdst[(row * 128 + c0) >> 1] = v;
            }
        }
    }
}

// ---------------------------------------------------------------------------
// reduce: sum 3 split partials, scatter to out[b][l][h][w].  392 CTAs.
// ---------------------------------------------------------------------------
__global__ __launch_bounds__(256) void reduce_kernel(float* __restrict__ out) {
    int tile = blockIdx.x >> 1;
    int half = blockIdx.x & 1;
    int mt = tile / NTT, nt = tile - mt * NTT;
    size_t base = (size_t)tile * 16384 + (size_t)half * 8192;
    const float4* p0 = reinterpret_cast<const float4*>(g_P + base);
    const float4* p1 = reinterpret_cast<const float4*>(g_P + base + (size_t)NTILES * 16384);
    const float4* p2 = reinterpret_cast<const float4*>(g_P + base + (size_t)(2 * NTILES) * 16384);

    int tid = threadIdx.x;
#pragma unroll
    for (int it = 0; it < 8; it++) {
        int v = it * 256 + tid;                // float4 index within half (2048)
        float4 a = p0[v], b4 = p1[v], c = p2[v];
        float s0 = a.x + b4.x + c.x;
        float s1 = a.y + b4.y + c.y;
        float s2 = a.z + b4.z + c.z;
        float s3 = a.w + b4.w + c.w;
        int idx = half * 8192 + v * 4;
        int row = idx >> 7, col = idx & 127;
        int m = mt * 128 + row;
        int n = nt * 128 + col;
        int bb = n / 49, hw = n - bb * 49;
        float* o = out + (size_t)m * 49;
        o[(size_t)bb * 25088 + hw] = s0; if (++hw == 49) { hw = 0; bb++; }
        o[(size_t)bb * 25088 + hw] = s1; if (++hw == 49) { hw = 0; bb++; }
        o[(size_t)bb * 25088 + hw] = s2; if (++hw == 49) { hw = 0; bb++; }
        o[(size_t)bb * 25088 + hw] = s3;
    }
}

// ---------------------------------------------------------------------------
extern "C" void kernel_launch(void* const* d_in, const int* in_sizes, int n_in,
                              void* d_out, int out_size) {
    const float* x  = (const float*)d_in[0];   // [128,512,7,7]
    const float* Wt = (const float*)d_in[1];   // [256,3,3,512]
    float* out = (float*)d_out;                // [128,512,7,7]

    cudaFuncSetAttribute(prep_kernel, cudaFuncAttributeMaxDynamicSharedMemorySize,
                         PREP_SMEM);
    cudaFuncSetAttribute(gemm_kernel, cudaFuncAttributeMaxDynamicSharedMemorySize,
                         GEMM_SMEM);

    prep_kernel<<<272, 512, PREP_SMEM>>>(x, Wt);
    gemm_kernel<<<KSPLIT * NTILES, 256, GEMM_SMEM>>>();
    reduce_kernel<<<2 * NTILES, 256>>>(out);
}

// round 15
// speedup vs baseline: 1.1259x; 1.0932x over previous
#include <cuda_runtime.h>
#include <cuda_fp16.h>
#include <cstdint>

// ---------------------------------------------------------------------------
// y[b,l,h,w] = sum_{j,k,i} A[(b,h,w),(j,k,i)] * W[j,k,i,l]
// GEMM: D[512, 6272] = Wmat[512,2304] * Amat[6272,2304]^T  (fp16 in, f32 acc)
// v15: GEMM mainloop syncthreads-free: empty-mbarriers (count 256) replace
// the per-stage __syncthreads; consumers arrive+proceed, only the producer
// waits for buffer-free.  Prep back to 256 threads (measured best).
// ---------------------------------------------------------------------------

#define NKC    72          // 2304 / 32 K blocks
#define MT     4           // M tiles of 128  (M = 512)
#define NTT    49          // N tiles of 128  (N = 6272)
#define NTILES 196         // MT * NTT
#define BLKB   8192        // one 128x32 fp16 tile block (128 rows x 64 B)
#define STAGE_BYTES 32768  // 64-K stage: 2 W blocks + 2 A blocks
#define STAGES 3
#define KSPLIT 3
#define NSTS   12          // 64-K stages per split (36 / 3)
#define GEMM_SMEM (1024 + STAGES * STAGE_BYTES)   // 99328 (x2 = 194K < 227K)

#define PREP_SMEM (25088 * 4)          // x[b] verbatim (100352 B)

__device__ __align__(128) unsigned char g_W[MT * NKC * BLKB];        // 2.36 MB
__device__ __align__(128) unsigned char g_A[NTT * NKC * BLKB];       // 28.9 MB
__device__ __align__(128) float g_P[KSPLIT * NTILES * 16384];        // 38.5 MB

// ---------------------------------------------------------------------------
// helpers
// ---------------------------------------------------------------------------
__device__ __forceinline__ uint32_t smem_u32(const void* p) {
    uint32_t a;
    asm("{ .reg .u64 t; cvta.to.shared.u64 t, %1; cvt.u32.u64 %0, t; }"
        : "=r"(a) : "l"(p));
    return a;
}
__device__ __forceinline__ void mbar_init(uint32_t a, uint32_t cnt) {
    asm volatile("mbarrier.init.shared.b64 [%0], %1;" :: "r"(a), "r"(cnt) : "memory");
}
__device__ __forceinline__ void mbar_expect_tx(uint32_t a, uint32_t bytes) {
    asm volatile("mbarrier.arrive.expect_tx.shared.b64 _, [%0], %1;"
                 :: "r"(a), "r"(bytes) : "memory");
}
__device__ __forceinline__ void mbar_arrive(uint32_t a) {
    asm volatile("mbarrier.arrive.shared.b64 _, [%0];" :: "r"(a) : "memory");
}
__device__ __forceinline__ void mbar_wait(uint32_t mbar, uint32_t parity) {
    uint32_t done;
    asm volatile("{\n\t.reg .pred p;\n\t"
                 "mbarrier.try_wait.parity.acquire.cta.shared::cta.b64 p, [%1], %2;\n\t"
                 "selp.b32 %0,1,0,p;\n\t}"
                 : "=r"(done) : "r"(mbar), "r"(parity) : "memory");
    while (!done) {
        asm volatile("{\n\t.reg .pred p;\n\t"
                     "mbarrier.try_wait.parity.acquire.cta.shared::cta.b64 p, [%1], %2, 0x989680;\n\t"
                     "selp.b32 %0,1,0,p;\n\t}"
                     : "=r"(done) : "r"(mbar), "r"(parity) : "memory");
    }
}
__device__ __forceinline__ void bulk_g2s(uint32_t dst, const void* src,
                                         uint32_t bytes, uint32_t mbar) {
    asm volatile("cp.async.bulk.shared::cluster.global.mbarrier::complete_tx::bytes "
                 "[%0], [%1], %2, [%3];"
                 :: "r"(dst), "l"(src), "r"(bytes), "r"(mbar) : "memory");
}
__device__ __forceinline__ void ldsm4(uint32_t* r, uint32_t addr) {
    asm volatile("ldmatrix.sync.aligned.m8n8.x4.shared.b16 {%0,%1,%2,%3}, [%4];"
                 : "=r"(r[0]), "=r"(r[1]), "=r"(r[2]), "=r"(r[3]) : "r"(addr));
}
__device__ __forceinline__ void mma16816(float* c, const uint32_t* a, const uint32_t* b) {
    asm volatile("mma.sync.aligned.m16n8k16.row.col.f32.f16.f16.f32 "
                 "{%0,%1,%2,%3}, {%4,%5,%6,%7}, {%8,%9}, {%0,%1,%2,%3};"
                 : "+f"(c[0]), "+f"(c[1]), "+f"(c[2]), "+f"(c[3])
                 : "r"(a[0]), "r"(a[1]), "r"(a[2]), "r"(a[3]),
                   "r"(b[0]), "r"(b[1]));
}
__device__ __forceinline__ uint32_t pack_f16x2(float lo, float hi) {
    uint32_t u;
    asm("cvt.rn.f16x2.f32 %0, %1, %2;" : "=r"(u) : "f"(hi), "f"(lo));
    return u;
}

// ---------------------------------------------------------------------------
// prep (256 threads): blocks [0,128) build g_A for batch b;
//                     blocks [128,272) build g_W (chunk-swizzled).
// ---------------------------------------------------------------------------
__global__ __launch_bounds__(256, 1) void prep_kernel(const float* __restrict__ x,
                                                      const float* __restrict__ Wt) {
    extern __shared__ float dynsm[];
    int tid = threadIdx.x;

    if (blockIdx.x >= 128) {
        // ---- wtrans: W[j,k,i,l] -> g_W fp16 [mt][ks][128 x 32] swizzled ----
        int t = blockIdx.x - 128;                   // 0..143
        int mt = t / 36;
        int K0 = (t - mt * 36) * 64;
        int L0 = mt * 128;
        int ks0 = K0 >> 5;
        float* ws = dynsm;                          // [64][129]

        int lx = tid & 127;
#pragma unroll
        for (int kl = (tid >> 7); kl < 64; kl += 2) {
            int kk = K0 + kl;
            int j = kk & 255, ki = kk >> 8;
            int k = (ki * 11) >> 5, i = ki - 3 * k;
            ws[kl * 129 + lx] = Wt[(size_t)((j * 3 + k) * 3 + i) * 512 + L0 + lx];
        }
        __syncthreads();

        int u = tid & 15;                           // u>>2 = chunk, u&3 = word
        int rbase = tid >> 4;
#pragma unroll
        for (int rr = 0; rr < 8; rr++) {
            int rloc = rr * 16 + rbase;
            uint32_t swc = ((uint32_t)(u >> 2) ^ ((rloc >> 1) & 3)) << 4;
#pragma unroll
            for (int ksb = 0; ksb < 2; ksb++) {
                float v0 = ws[(ksb * 32 + 2 * u) * 129 + rloc];
                float v1 = ws[(ksb * 32 + 2 * u + 1) * 129 + rloc];
                *reinterpret_cast<uint32_t*>(
                    g_W + (size_t)(mt * NKC + ks0 + ksb) * BLKB
                    + rloc * 64 + swc + (u & 3) * 4) = pack_f16x2(v0, v1);
            }
        }
        return;
    }

    // ---- A build for batch b ----
    float* xs = dynsm;                              // x[b] verbatim: xs[c*49+hw]
    int b = blockIdx.x;
    const float4* xb4 = reinterpret_cast<const float4*>(x + (size_t)b * 25088);
    float4* xs4 = reinterpret_cast<float4*>(xs);

    // Phase 1: verbatim copy (coalesced, conflict-free, full MLP)
    for (int v = tid; v < 6272; v += 256) xs4[v] = xb4[v];
    __syncthreads();

    int wid = tid >> 5, lane = tid & 31;

    // Phase 2: 77 (s,w2) combos, s in 1..11.  Warp computes the 512B D-row
    // in registers (lane: j = 8*lane .. 8*lane+7, strided LDS) and scatters.
    for (int combo = wid; combo < 77; combo += 8) {
        int s = combo / 7 + 1, w2 = combo - (s - 1) * 7;
        int rpA, rpB;
        if (s < 9) { rpA = s - 1; rpB = s - 2; }
        else       { rpA = s - 10; rpB = s - 4; }
        bool g1 = (unsigned)rpA < 7u, g2 = (unsigned)rpB < 7u;

        float va[8], vb[8];
#pragma unroll
        for (int jj = 0; jj < 8; jj++) { va[jj] = 0.f; vb[jj] = 0.f; }
        if (g1) {
            const float* p = xs + (lane * 8) * 49 + rpA * 7 + w2;
#pragma unroll
            for (int jj = 0; jj < 8; jj++) va[jj] = p[jj * 49];
        }
        if (g2) {
            const float* p = xs + (256 + lane * 8) * 49 + rpB * 7 + w2;
#pragma unroll
            for (int jj = 0; jj < 8; jj++) vb[jj] = p[jj * 49];
        }
        uint4 o;
        o.x = pack_f16x2(va[0] + vb[0], va[1] + vb[1]);
        o.y = pack_f16x2(va[2] + vb[2], va[3] + vb[3]);
        o.z = pack_f16x2(va[4] + vb[4], va[5] + vb[5]);
        o.w = pack_f16x2(va[6] + vb[6], va[7] + vb[7]);

        int ww1 = (w2 + 1) % 7;
        int jc = lane >> 2, cw = lane & 3;
        int hlo, hhi;
        if (s >= 9) { hlo = 0; hhi = 0; }
        else { hlo = (s - 2 > 1) ? s - 2 : 1; hhi = (s < 6) ? s : 6; }
#pragma unroll 1
        for (int h = hlo; h <= hhi; h++) {
            int k = (s >= 9) ? (s - 9) : (s - h);
#pragma unroll
            for (int i = 0; i < 3; i++) {
                int w = ww1 + 1 - i;
                if ((unsigned)w < 7u) {
                    int ki = k * 3 + i;
                    int n = b * 49 + h * 7 + w;
                    int nt = n >> 7, row = n & 127;
                    int chunk = cw ^ ((row >> 1) & 3);
                    *reinterpret_cast<uint4*>(
                        g_A + ((size_t)(nt * NKC + ki * 8 + jc) << 13)
                        + row * 64 + chunk * 16) = o;
                }
            }
        }
    }

    // Phase 3: zero the gated rows: (w=0,i=0) and (w=6,i=2), all h,k,jc.
    const uint4 z4 = {0, 0, 0, 0};
    for (int t = tid; t < 1344; t += 256) {
        int c = t & 3;
        int rown = t >> 2;                  // 0..335
        int jc = rown & 7;
        int zz = rown >> 3;                 // 0..41
        int zi = zz / 21;                   // 0:(w=0,i=0)  1:(w=6,i=2)
        int rem = zz - zi * 21;
        int k = rem / 7, h = rem - k * 7;
        int ki = k * 3 + (zi ? 2 : 0);
        int w = zi ? 6 : 0;
        int n = b * 49 + h * 7 + w;
        int nt = n >> 7, row = n & 127;
        *reinterpret_cast<uint4*>(
            g_A + ((size_t)(nt * NKC + ki * 8 + jc) << 13)
            + row * 64 + c * 16) = z4;
    }
}

// ---------------------------------------------------------------------------
// GEMM.  588 CTAs = 3 splits x (4 mt x 49 nt), tile 128x128 x K768.
// 12 stages of K=64 (32KB), 3-deep.  NO per-stage __syncthreads: consumers
// mbarrier.arrive on the stage's empty barrier (count 256) and run ahead;
// only the producer thread waits for buffer-free before its bulk copies.
// ---------------------------------------------------------------------------
__global__ __launch_bounds__(256, 2) void gemm_kernel() {
    extern __shared__ __align__(1024) unsigned char smem[];
    uint32_t sb = smem_u32(smem);
    const uint32_t FULLB = sb;                 // 3 x 8B full barriers
    const uint32_t EMPTYB = sb + 24;           // 3 x 8B empty barriers
    const uint32_t DATA = sb + 1024;

    int tid = threadIdx.x, wid = tid >> 5, lane = tid & 31;
    int sp = blockIdx.x / NTILES;
    int tile = blockIdx.x - sp * NTILES;
    int mt = tile / NTT, nt = tile - mt * NTT;
    int wm = wid & 1, wn = wid >> 1;           // 2(M) x 4(N)

    const unsigned char* wsrc = g_W + (size_t)mt * NKC * BLKB
                                + (size_t)sp * NSTS * 16384;
    const unsigned char* asrc = g_A + (size_t)nt * NKC * BLKB
                                + (size_t)sp * NSTS * 16384;

    if (tid == 0) {
#pragma unroll
        for (int s = 0; s < STAGES; s++) {
            mbar_init(FULLB + 8 * s, 1);
            mbar_init(EMPTYB + 8 * s, 256);
        }
    }
    asm volatile("fence.proxy.async.shared::cta;" ::: "memory");
    __syncthreads();

    if (tid == 0) {
#pragma unroll
        for (int ip = 0; ip < STAGES - 1; ip++) {
            uint32_t mb = FULLB + 8 * ip;
            mbar_expect_tx(mb, STAGE_BYTES);
            bulk_g2s(DATA + ip * STAGE_BYTES, wsrc + (size_t)ip * 16384, 16384, mb);
            bulk_g2s(DATA + ip * STAGE_BYTES + 16384, asrc + (size_t)ip * 16384, 16384, mb);
        }
    }

    // ldsm per-thread addressing (chunk swizzle: ^ ((row>>1)&3))
    uint32_t arow = wm * 64 + (lane & 15);
    uint32_t axor = (arow >> 1) & 3;
    uint32_t ahi = lane >> 4;
    uint32_t aoffb = arow * 64;
    uint32_t brow = wn * 32 + (lane & 7) + ((lane & 16) >> 1);
    uint32_t bxor = (brow >> 1) & 3;
    uint32_t bhi = (lane >> 3) & 1;
    uint32_t boffb = brow * 64;

    float acc[4][4][4];
#pragma unroll
    for (int mi = 0; mi < 4; mi++)
#pragma unroll
        for (int ni = 0; ni < 4; ni++)
#pragma unroll
            for (int r = 0; r < 4; r++) acc[mi][ni][r] = 0.f;

#pragma unroll 1
    for (int st = 0; st < NSTS; st++) {
        int buf = st % 3;
        mbar_wait(FULLB + 8 * buf, (uint32_t)((st / 3) & 1));

        // producer: issue stage st+2 (its buffer freed by stage st-1 arrivals)
        if (tid == 0) {
            int ip = st + STAGES - 1;
            if (ip < NSTS) {
                int pb = ip % 3;
                if (ip >= STAGES)
                    mbar_wait(EMPTYB + 8 * pb, (uint32_t)(((ip / 3) - 1) & 1));
                uint32_t mb = FULLB + 8 * pb;
                mbar_expect_tx(mb, STAGE_BYTES);
                bulk_g2s(DATA + pb * STAGE_BYTES, wsrc + (size_t)ip * 16384, 16384, mb);
                bulk_g2s(DATA + pb * STAGE_BYTES + 16384, asrc + (size_t)ip * 16384, 16384, mb);
            }
        }

        uint32_t sbuf = DATA + buf * STAGE_BYTES;
#pragma unroll
        for (int kst = 0; kst < 4; kst++) {
            uint32_t wbo = (uint32_t)(kst >> 1) * 8192;
            uint32_t ac = (((kst & 1) * 2 + ahi) ^ axor) << 4;
            uint32_t bc = (((kst & 1) * 2 + bhi) ^ bxor) << 4;
            uint32_t a[4][4], bfr[2][4];
#pragma unroll
            for (int mi = 0; mi < 4; mi++)
                ldsm4(a[mi], sbuf + wbo + aoffb + mi * 1024 + ac);
#pragma unroll
            for (int np = 0; np < 2; np++)
                ldsm4(bfr[np], sbuf + 16384 + wbo + boffb + np * 1024 + bc);
#pragma unroll
            for (int mi = 0; mi < 4; mi++)
#pragma unroll
                for (int ni = 0; ni < 4; ni++)
                    mma16816(acc[mi][ni], a[mi], &bfr[ni >> 1][(ni & 1) * 2]);
        }

        // done reading this buffer (all reads consumed by mma issues above)
        mbar_arrive(EMPTYB + 8 * buf);
    }

    // epilogue: dense f32 partial tile, float2 stores
    float2* pdst = reinterpret_cast<float2*>(g_P + (size_t)blockIdx.x * 16384);
#pragma unroll
    for (int mi = 0; mi < 4; mi++) {
        int r0 = wm * 64 + mi * 16 + (lane >> 2);
#pragma unroll
        for (int ni = 0; ni < 4; ni++) {
            int c0 = wn * 32 + ni * 8 + 2 * (lane & 3);
#pragma unroll
            for (int rp = 0; rp < 2; rp++) {
                int row = r0 + rp * 8;
                float2 v = { acc[mi][ni][rp * 2], acc[mi][ni][rp * 2 + 1] };
                pdst[(row * 128 + c0) >> 1] = v;
            }
        }
    }
}

// ---------------------------------------------------------------------------
// reduce: sum 3 split partials, scatter to out[b][l][h][w].  392 CTAs.
// ---------------------------------------------------------------------------
__global__ __launch_bounds__(256) void reduce_kernel(float* __restrict__ out) {
    int tile = blockIdx.x >> 1;
    int half = blockIdx.x & 1;
    int mt = tile / NTT, nt = tile - mt * NTT;
    size_t base = (size_t)tile * 16384 + (size_t)half * 8192;
    const float4* p0 = reinterpret_cast<const float4*>(g_P + base);
    const float4* p1 = reinterpret_cast<const float4*>(g_P + base + (size_t)NTILES * 16384);
    const float4* p2 = reinterpret_cast<const float4*>(g_P + base + (size_t)(2 * NTILES) * 16384);

    int tid = threadIdx.x;
#pragma unroll
    for (int it = 0; it < 8; it++) {
        int v = it * 256 + tid;                // float4 index within half (2048)
        float4 a = p0[v], b4 = p1[v], c = p2[v];
        float s0 = a.x + b4.x + c.x;
        float s1 = a.y + b4.y + c.y;
        float s2 = a.z + b4.z + c.z;
        float s3 = a.w + b4.w + c.w;
        int idx = half * 8192 + v * 4;
        int row = idx >> 7, col = idx & 127;
        int m = mt * 128 + row;
        int n = nt * 128 + col;
        int bb = n / 49, hw = n - bb * 49;
        float* o = out + (size_t)m * 49;
        o[(size_t)bb * 25088 + hw] = s0; if (++hw == 49) { hw = 0; bb++; }
        o[(size_t)bb * 25088 + hw] = s1; if (++hw == 49) { hw = 0; bb++; }
        o[(size_t)bb * 25088 + hw] = s2; if (++hw == 49) { hw = 0; bb++; }
        o[(size_t)bb * 25088 + hw] = s3;
    }
}

// ---------------------------------------------------------------------------
extern "C" void kernel_launch(void* const* d_in, const int* in_sizes, int n_in,
                              void* d_out, int out_size) {
    const float* x  = (const float*)d_in[0];   // [128,512,7,7]
    const float* Wt = (const float*)d_in[1];   // [256,3,3,512]
    float* out = (float*)d_out;                // [128,512,7,7]

    cudaFuncSetAttribute(prep_kernel, cudaFuncAttributeMaxDynamicSharedMemorySize,
                         PREP_SMEM);
    cudaFuncSetAttribute(gemm_kernel, cudaFuncAttributeMaxDynamicSharedMemorySize,
                         GEMM_SMEM);

    prep_kernel<<<272, 256, PREP_SMEM>>>(x, Wt);
    gemm_kernel<<<KSPLIT * NTILES, 256, GEMM_SMEM>>>();
    reduce_kernel<<<2 * NTILES, 256>>>(out);
}